// round 11
// baseline (speedup 1.0000x reference)
#include <cuda_runtime.h>
#include <math.h>

#define NMAX 100000
#define ACC_W 16   // [coeff, edge_sca*coeff (6), edge_vec*coeff (9)]
#define EPB 256    // edges per block in edge kernel

__device__ __align__(16) float g_acc[NMAX * ACC_W];   // zero-initialized at load

typedef unsigned long long u64;
__device__ __forceinline__ u64 pk(float lo, float hi) {
    u64 r; asm("mov.b64 %0, {%1,%2};" : "=l"(r) : "f"(lo), "f"(hi)); return r;
}
__device__ __forceinline__ void upk(u64 v, float& lo, float& hi) {
    asm("mov.b64 {%0,%1}, %2;" : "=f"(lo), "=f"(hi) : "l"(v));
}
__device__ __forceinline__ void fma2(u64& d, u64 a, u64 b) {
    asm("fma.rn.f32x2 %0, %1, %2, %0;" : "+l"(d) : "l"(a), "l"(b));
}
__device__ __forceinline__ void mul2(u64& d, u64 a) {
    asm("mul.rn.f32x2 %0, %0, %1;" : "+l"(d) : "l"(a));
}

// ---------------------------------------------------------------------------
// Edge phase (unchanged): staged coalesced loads + red.v4
// ---------------------------------------------------------------------------
__device__ __forceinline__ void red_v4(float* p, float a, float b, float c, float d) {
    asm volatile("red.global.add.v4.f32 [%0], {%1,%2,%3,%4};"
                 :: "l"(p), "f"(a), "f"(b), "f"(c), "f"(d) : "memory");
}

__global__ void __launch_bounds__(EPB)
edge_kernel(const float* __restrict__ edge_sca,
            const float* __restrict__ edge_vec,
            const float* __restrict__ gds,
            const int*   __restrict__ src_idx,
            int E) {
    __shared__ float s_sca[EPB * 6];
    __shared__ float s_vec[EPB * 9];

    int blockStart = blockIdx.x * EPB;
    int tid = threadIdx.x;
    int nEdges = min(EPB, E - blockStart);

    if (nEdges == EPB) {
        const float4* g4s = (const float4*)(edge_sca + (size_t)blockStart * 6);
        float4* s4s = (float4*)s_sca;
#pragma unroll 2
        for (int i = tid; i < (EPB * 6) / 4; i += EPB)
            s4s[i] = g4s[i];
        const float4* g4v = (const float4*)(edge_vec + (size_t)blockStart * 9);
        float4* s4v = (float4*)s_vec;
#pragma unroll 3
        for (int i = tid; i < (EPB * 9) / 4; i += EPB)
            s4v[i] = g4v[i];
    } else {
        for (int i = tid; i < nEdges * 6; i += EPB)
            s_sca[i] = edge_sca[(size_t)blockStart * 6 + i];
        for (int i = tid; i < nEdges * 9; i += EPB)
            s_vec[i] = edge_vec[(size_t)blockStart * 9 + i];
    }
    __syncthreads();

    if (tid >= nEdges) return;
    int e = blockStart + tid;

    float dist = __ldg(gds + e);
    if (dist > 10.0f || dist < 0.0f) return;
    float coeff = 0.5f * (__cosf(dist * 0.31415926535f) + 1.0f);

    int src = __ldg(src_idx + e);

    float es[6];
#pragma unroll
    for (int c = 0; c < 6; c++) es[c] = s_sca[tid * 6 + c] * coeff;
    float ev[9];
#pragma unroll
    for (int c = 0; c < 9; c++) ev[c] = s_vec[tid * 9 + c] * coeff;

    float* base = g_acc + (size_t)src * ACC_W;
    red_v4(base + 0,  coeff, es[0], es[1], es[2]);
    red_v4(base + 4,  es[3], es[4], es[5], ev[0]);
    red_v4(base + 8,  ev[1], ev[2], ev[3], ev[4]);
    red_v4(base + 12, ev[5], ev[6], ev[7], ev[8]);
}

// ---------------------------------------------------------------------------
// Node phase: 2 nodes/thread, phases 2/5/6 use packed fma.rn.f32x2 with
// pre-duplicated (w,w) weights in smem.
// ---------------------------------------------------------------------------
#define O_NSS   0      // 4x16
#define O_BNSS  64     // 16
#define O_ESS   80     // 6x16
#define O_BESS  176    // 16
#define O_NSV   192    // 4x16
#define O_BNSV  256    // 16
#define O_ESV   272    // 6x16
#define O_BESV  368    // 16
#define O_NVV   384    // 3x16
#define O_EVV   432    // 3x16
#define O_LS    480    // 32x16 (full; phase 3 uses lower rows scalar)
#define O_GATE  992    // 16x16
#define O_BGATE 1248   // 16
#define SW_TOT  1264

#define NPB 64         // nodes per block
#define TPB 128        // threads (4 lanes x 32 node-pairs)
#define HALF_ND 32
#define BUF_W 68       // 64 payload + 4 pad floats

__global__ void __launch_bounds__(TPB)
node_kernel(const float* __restrict__ node_sca,
            const float* __restrict__ node_vec,
            const float* __restrict__ W_nss, const float* __restrict__ b_nss,
            const float* __restrict__ W_ess, const float* __restrict__ b_ess,
            const float* __restrict__ W_nsv, const float* __restrict__ b_nsv,
            const float* __restrict__ W_esv, const float* __restrict__ b_esv,
            const float* __restrict__ W_nvv, const float* __restrict__ W_evv,
            const float* __restrict__ W_lv,  const float* __restrict__ W_lv2,
            const float* __restrict__ W_ls,  const float* __restrict__ W_gate,
            const float* __restrict__ b_gate,const float* __restrict__ W_dir,
            float* __restrict__ out, int N) {
    __shared__ __align__(16) float sW[SW_TOT];
    __shared__ float s_nv[NPB * 9];
    __shared__ __align__(16) float bufA[NPB][BUF_W];  // aggr -> osca -> ovec
    __shared__ __align__(16) float bufB[NPB][BUF_W];  // v_inter + v_norm
    // duplicated (w,w) weights for packed FMA phases
    __shared__ __align__(16) float2 sDlv[256];
    __shared__ __align__(16) float2 sDlsU[256];   // W_ls rows 16..31
    __shared__ __align__(16) float2 sDlv2[256];
    __shared__ __align__(16) float2 sDdir[256];

    int tid = threadIdx.x;
    int ndA = tid >> 2;
    int ndB = ndA + HALF_ND;
    int j   = tid & 3;
    int o0  = j * 4;
    int blockStart = blockIdx.x * NPB;
    int nNodes = min(NPB, N - blockStart);
    int nA = blockStart + ndA;
    int nB = blockStart + ndB;
    bool actA = (ndA < nNodes);
    bool actB = (ndB < nNodes);

    {   // scalar weights -> shared
        const float* srcs[13] = {W_nss, b_nss, W_ess, b_ess, W_nsv, b_nsv,
                                 W_esv, b_esv, W_nvv, W_evv, W_ls, W_gate, b_gate};
        const int offs[14] = {O_NSS, O_BNSS, O_ESS, O_BESS, O_NSV, O_BNSV,
                              O_ESV, O_BESV, O_NVV, O_EVV, O_LS, O_GATE,
                              O_BGATE, SW_TOT};
        for (int a = 0; a < 13; a++) {
            int cnt = offs[a + 1] - offs[a];
            for (int i = tid; i < cnt; i += TPB)
                sW[offs[a] + i] = srcs[a][i];
        }
        // duplicated weights
        for (int i = tid; i < 256; i += TPB) {
            float w1 = W_lv[i];        sDlv[i]  = make_float2(w1, w1);
            float w2 = W_ls[256 + i];  sDlsU[i] = make_float2(w2, w2);
            float w3 = W_lv2[i];       sDlv2[i] = make_float2(w3, w3);
            float w4 = W_dir[i];       sDdir[i] = make_float2(w4, w4);
        }
    }
    {   // node_vec -> shared (coalesced)
        for (int i = tid; i < nNodes * 9; i += TPB)
            s_nv[i] = node_vec[(size_t)blockStart * 9 + i];
    }
    __syncthreads();

    // ---- Phase 1 per node (scalar, inputs transient) ----
#pragma unroll
    for (int half = 0; half < 2; half++) {
        int nd = half ? ndB : ndA;
        int n  = half ? nB  : nA;
        bool act = half ? actB : actA;
        if (!act) continue;

        float4 ns4 = ((const float4*)node_sca)[n];
        float ns[4] = {ns4.x, ns4.y, ns4.z, ns4.w};
        float nv[9];
#pragma unroll
        for (int i = 0; i < 9; i++) nv[i] = s_nv[nd * 9 + i];
        float accv[16];
        {
            float4* a4 = (float4*)(g_acc + (size_t)n * ACC_W);
#pragma unroll
            for (int q = 0; q < 4; q++) {
                float4 v = a4[q];
                accv[q * 4 + 0] = v.x; accv[q * 4 + 1] = v.y;
                accv[q * 4 + 2] = v.z; accv[q * 4 + 3] = v.w;
            }
            a4[j] = make_float4(0.f, 0.f, 0.f, 0.f);   // reset quarter j
        }
        float Cs = accv[0];
        float* Es = accv + 1;
        float* Ev = accv + 7;

#pragma unroll
        for (int cc = 0; cc < 4; cc++) {
            int c = o0 + cc;
            float nss = sW[O_BNSS + c];
            float nsv = sW[O_BNSV + c];
#pragma unroll
            for (int k = 0; k < 4; k++) {
                nss += ns[k] * sW[O_NSS + k * 16 + c];
                nsv += ns[k] * sW[O_NSV + k * 16 + c];
            }
            float ess = sW[O_BESS + c] * Cs;
            float esv = sW[O_BESV + c] * Cs;
#pragma unroll
            for (int k = 0; k < 6; k++) {
                ess += Es[k] * sW[O_ESS + k * 16 + c];
                esv += Es[k] * sW[O_ESV + k * 16 + c];
            }
            float av[3];
#pragma unroll
            for (int i = 0; i < 3; i++) {
                float nvv = 0.f, evv = 0.f;
#pragma unroll
                for (int k = 0; k < 3; k++) {
                    nvv += nv[k * 3 + i] * sW[O_NVV + k * 16 + c];
                    evv += Ev[k * 3 + i] * sW[O_EVV + k * 16 + c];
                }
                av[i] = nvv * esv + nsv * evv;
            }
            *(float4*)&bufA[nd][c * 4] = make_float4(av[0], av[1], av[2], nss * ess);
        }
    }
    __syncwarp();

    // ---- Phase 2: lv + ls-scalar-half, packed f32x2 over (A,B) ----
    u64 vi[4][3];
    u64 os2[4];
#pragma unroll
    for (int oo = 0; oo < 4; oo++) {
        vi[oo][0] = vi[oo][1] = vi[oo][2] = 0ull;
        os2[oo] = 0ull;
    }
#pragma unroll
    for (int c = 0; c < 16; c++) {
        float4 a = *(const float4*)&bufA[ndA][c * 4];
        float4 b = *(const float4*)&bufA[ndB][c * 4];
        u64 px = pk(a.x, b.x), py = pk(a.y, b.y), pz = pk(a.z, b.z), pw = pk(a.w, b.w);
        ulonglong2 w01 = *(const ulonglong2*)&sDlv[c * 16 + o0];
        ulonglong2 w23 = *(const ulonglong2*)&sDlv[c * 16 + o0 + 2];
        fma2(vi[0][0], px, w01.x); fma2(vi[0][1], py, w01.x); fma2(vi[0][2], pz, w01.x);
        fma2(vi[1][0], px, w01.y); fma2(vi[1][1], py, w01.y); fma2(vi[1][2], pz, w01.y);
        fma2(vi[2][0], px, w23.x); fma2(vi[2][1], py, w23.x); fma2(vi[2][2], pz, w23.x);
        fma2(vi[3][0], px, w23.y); fma2(vi[3][1], py, w23.y); fma2(vi[3][2], pz, w23.y);
        ulonglong2 s01 = *(const ulonglong2*)&sDlsU[c * 16 + o0];
        ulonglong2 s23 = *(const ulonglong2*)&sDlsU[c * 16 + o0 + 2];
        fma2(os2[0], pw, s01.x); fma2(os2[1], pw, s01.y);
        fma2(os2[2], pw, s23.x); fma2(os2[3], pw, s23.y);
    }
    float oscaA[4], oscaB[4];
#pragma unroll
    for (int oo = 0; oo < 4; oo++) {
        u64 n2 = 0ull;
        fma2(n2, vi[oo][0], vi[oo][0]);
        fma2(n2, vi[oo][1], vi[oo][1]);
        fma2(n2, vi[oo][2], vi[oo][2]);
        float nA, nB; upk(n2, nA, nB);
        float xA, xB, yA, yB, zA, zB;
        upk(vi[oo][0], xA, xB); upk(vi[oo][1], yA, yB); upk(vi[oo][2], zA, zB);
        *(float4*)&bufB[ndA][(o0 + oo) * 4] = make_float4(xA, yA, zA, sqrtf(nA));
        *(float4*)&bufB[ndB][(o0 + oo) * 4] = make_float4(xB, yB, zB, sqrtf(nB));
        upk(os2[oo], oscaA[oo], oscaB[oo]);
    }
    __syncwarp();

    // ---- Phase 3: osca v_norm-half (scalar); publish osca ----
#pragma unroll
    for (int c = 0; c < 16; c++) {
        float4 wls = *(const float4*)&sW[O_LS + c * 16 + o0];
        float vnA = bufB[ndA][c * 4 + 3];
        float vnB = bufB[ndB][c * 4 + 3];
        oscaA[0] += vnA * wls.x; oscaA[1] += vnA * wls.y;
        oscaA[2] += vnA * wls.z; oscaA[3] += vnA * wls.w;
        oscaB[0] += vnB * wls.x; oscaB[1] += vnB * wls.y;
        oscaB[2] += vnB * wls.z; oscaB[3] += vnB * wls.w;
    }
    *(float4*)&bufA[ndA][o0] = make_float4(oscaA[0], oscaA[1], oscaA[2], oscaA[3]);
    *(float4*)&bufA[ndB][o0] = make_float4(oscaB[0], oscaB[1], oscaB[2], oscaB[3]);
    __syncwarp();

    // ---- Phase 4: gate (scalar, small) ----
    float gateA[4], gateB[4];
#pragma unroll
    for (int oo = 0; oo < 4; oo++) gateA[oo] = gateB[oo] = sW[O_BGATE + o0 + oo];
#pragma unroll
    for (int c4 = 0; c4 < 4; c4++) {
        float4 ocA = *(const float4*)&bufA[ndA][c4 * 4];
        float4 ocB = *(const float4*)&bufA[ndB][c4 * 4];
        float av[4] = {ocA.x, ocA.y, ocA.z, ocA.w};
        float bv[4] = {ocB.x, ocB.y, ocB.z, ocB.w};
#pragma unroll
        for (int q = 0; q < 4; q++) {
            float4 wg = *(const float4*)&sW[O_GATE + (c4 * 4 + q) * 16 + o0];
            gateA[0] += av[q] * wg.x; gateA[1] += av[q] * wg.y;
            gateA[2] += av[q] * wg.z; gateA[3] += av[q] * wg.w;
            gateB[0] += bv[q] * wg.x; gateB[1] += bv[q] * wg.y;
            gateB[2] += bv[q] * wg.z; gateB[3] += bv[q] * wg.w;
        }
    }
#pragma unroll
    for (int oo = 0; oo < 4; oo++) {
        gateA[oo] = 1.0f / (1.0f + __expf(-gateA[oo]));
        gateB[oo] = 1.0f / (1.0f + __expf(-gateB[oo]));
    }
    __syncwarp();   // osca reads done; bufA reusable for ovec

    // ---- Phase 5: lv2 -> ovec (gated), packed ----
    u64 ov2[4][3];
#pragma unroll
    for (int oo = 0; oo < 4; oo++) ov2[oo][0] = ov2[oo][1] = ov2[oo][2] = 0ull;
#pragma unroll
    for (int c = 0; c < 16; c++) {
        float4 vA = *(const float4*)&bufB[ndA][c * 4];
        float4 vB = *(const float4*)&bufB[ndB][c * 4];
        u64 px = pk(vA.x, vB.x), py = pk(vA.y, vB.y), pz = pk(vA.z, vB.z);
        ulonglong2 w01 = *(const ulonglong2*)&sDlv2[c * 16 + o0];
        ulonglong2 w23 = *(const ulonglong2*)&sDlv2[c * 16 + o0 + 2];
        fma2(ov2[0][0], px, w01.x); fma2(ov2[0][1], py, w01.x); fma2(ov2[0][2], pz, w01.x);
        fma2(ov2[1][0], px, w01.y); fma2(ov2[1][1], py, w01.y); fma2(ov2[1][2], pz, w01.y);
        fma2(ov2[2][0], px, w23.x); fma2(ov2[2][1], py, w23.x); fma2(ov2[2][2], pz, w23.x);
        fma2(ov2[3][0], px, w23.y); fma2(ov2[3][1], py, w23.y); fma2(ov2[3][2], pz, w23.y);
    }
#pragma unroll
    for (int oo = 0; oo < 4; oo++) {
        u64 g = pk(gateA[oo], gateB[oo]);
        mul2(ov2[oo][0], g); mul2(ov2[oo][1], g); mul2(ov2[oo][2], g);
        float xA, xB, yA, yB, zA, zB;
        upk(ov2[oo][0], xA, xB); upk(ov2[oo][1], yA, yB); upk(ov2[oo][2], zA, zB);
        *(float4*)&bufA[ndA][(o0 + oo) * 4] = make_float4(xA, yA, zA, 0.f);
        *(float4*)&bufA[ndB][(o0 + oo) * 4] = make_float4(xB, yB, zB, 0.f);
    }
    __syncwarp();

    // ---- Phase 6: direction (packed) + VNLeakyReLU + writes ----
    u64 d2[4][3];
#pragma unroll
    for (int oo = 0; oo < 4; oo++) d2[oo][0] = d2[oo][1] = d2[oo][2] = 0ull;
#pragma unroll
    for (int c = 0; c < 16; c++) {
        float4 vA = *(const float4*)&bufA[ndA][c * 4];
        float4 vB = *(const float4*)&bufA[ndB][c * 4];
        u64 px = pk(vA.x, vB.x), py = pk(vA.y, vB.y), pz = pk(vA.z, vB.z);
        ulonglong2 w01 = *(const ulonglong2*)&sDdir[c * 16 + o0];
        ulonglong2 w23 = *(const ulonglong2*)&sDdir[c * 16 + o0 + 2];
        fma2(d2[0][0], px, w01.x); fma2(d2[0][1], py, w01.x); fma2(d2[0][2], pz, w01.x);
        fma2(d2[1][0], px, w01.y); fma2(d2[1][1], py, w01.y); fma2(d2[1][2], pz, w01.y);
        fma2(d2[2][0], px, w23.x); fma2(d2[2][1], py, w23.x); fma2(d2[2][2], pz, w23.x);
        fma2(d2[3][0], px, w23.y); fma2(d2[3][1], py, w23.y); fma2(d2[3][2], pz, w23.y);
    }

    float resA[12], resB[12];
#pragma unroll
    for (int oo = 0; oo < 4; oo++) {
        float vxA, vxB, vyA, vyB, vzA, vzB;
        upk(ov2[oo][0], vxA, vxB); upk(ov2[oo][1], vyA, vyB); upk(ov2[oo][2], vzA, vzB);
        float dxA, dxB, dyA, dyB, dzA, dzB;
        upk(d2[oo][0], dxA, dxB); upk(d2[oo][1], dyA, dyB); upk(d2[oo][2], dzA, dzB);
        {
            float dot = vxA * dxA + vyA * dyA + vzA * dzA;
            float r0 = vxA, r1 = vyA, r2 = vzA;
            if (dot < 0.0f) {
                float k = 0.8f * dot / (dxA * dxA + dyA * dyA + dzA * dzA + 1e-6f);
                r0 -= k * dxA; r1 -= k * dyA; r2 -= k * dzA;
            }
            resA[oo * 3 + 0] = r0; resA[oo * 3 + 1] = r1; resA[oo * 3 + 2] = r2;
        }
        {
            float dot = vxB * dxB + vyB * dyB + vzB * dzB;
            float r0 = vxB, r1 = vyB, r2 = vzB;
            if (dot < 0.0f) {
                float k = 0.8f * dot / (dxB * dxB + dyB * dyB + dzB * dzB + 1e-6f);
                r0 -= k * dxB; r1 -= k * dyB; r2 -= k * dzB;
            }
            resB[oo * 3 + 0] = r0; resB[oo * 3 + 1] = r1; resB[oo * 3 + 2] = r2;
        }
    }

    float* out_vec = out + (size_t)N * 16;
#pragma unroll
    for (int half = 0; half < 2; half++) {
        bool act = half ? actB : actA;
        if (!act) continue;
        int n = half ? nB : nA;
        float* res  = half ? resB : resA;
        float* osca = half ? oscaB : oscaA;

        float4* dv = (float4*)(out_vec + (size_t)n * 48 + j * 12);
#pragma unroll
        for (int q = 0; q < 3; q++)
            dv[q] = make_float4(res[q * 4 + 0], res[q * 4 + 1],
                                res[q * 4 + 2], res[q * 4 + 3]);

        float s0 = osca[0], s1 = osca[1], s2 = osca[2], s3 = osca[3];
        s0 = (s0 >= 0.f) ? s0 : 0.01f * s0;
        s1 = (s1 >= 0.f) ? s1 : 0.01f * s1;
        s2 = (s2 >= 0.f) ? s2 : 0.01f * s2;
        s3 = (s3 >= 0.f) ? s3 : 0.01f * s3;
        ((float4*)(out + (size_t)n * 16 + o0))[0] = make_float4(s0, s1, s2, s3);
    }
}

// ---------------------------------------------------------------------------
extern "C" void kernel_launch(void* const* d_in, const int* in_sizes, int n_in,
                              void* d_out, int out_size) {
    const float* node_sca = (const float*)d_in[0];
    const float* node_vec = (const float*)d_in[1];
    const float* edge_sca = (const float*)d_in[2];
    const float* edge_vec = (const float*)d_in[3];
    const float* gds      = (const float*)d_in[4];
    const int*   ei       = (const int*)d_in[5];   // [2,E]; row 0 = src
    const float* W_nss  = (const float*)d_in[6];
    const float* b_nss  = (const float*)d_in[7];
    const float* W_ess  = (const float*)d_in[8];
    const float* b_ess  = (const float*)d_in[9];
    const float* W_nsv  = (const float*)d_in[10];
    const float* b_nsv  = (const float*)d_in[11];
    const float* W_esv  = (const float*)d_in[12];
    const float* b_esv  = (const float*)d_in[13];
    const float* W_nvv  = (const float*)d_in[14];
    const float* W_evv  = (const float*)d_in[15];
    const float* W_lv   = (const float*)d_in[16];
    const float* W_lv2  = (const float*)d_in[17];
    const float* W_ls   = (const float*)d_in[18];
    const float* W_gate = (const float*)d_in[19];
    const float* b_gate = (const float*)d_in[20];
    const float* W_dir  = (const float*)d_in[21];

    int N = in_sizes[0] / 4;
    int E = in_sizes[4];

    int eblocks = (E + EPB - 1) / EPB;
    edge_kernel<<<eblocks, EPB>>>(edge_sca, edge_vec, gds, ei, E);

    int nblocks = (N + NPB - 1) / NPB;
    node_kernel<<<nblocks, TPB>>>(node_sca, node_vec,
                                  W_nss, b_nss, W_ess, b_ess,
                                  W_nsv, b_nsv, W_esv, b_esv,
                                  W_nvv, W_evv, W_lv, W_lv2,
                                  W_ls, W_gate, b_gate, W_dir,
                                  (float*)d_out, N);
}